// round 6
// baseline (speedup 1.0000x reference)
#include <cuda_runtime.h>

#define EPS 1e-6f

// x: (2048, 4096, 16) fp32  -> 8,388,608 rows of 16 floats (64 B each)
// Grade slices over last dim: [0,1) [1,5) [5,11) [11,15) [15,16)
// out[..., a:b] = x[..., a:b] * rsqrt(sum(x[a:b]^2) + eps) * scale[g]
//
// HBM-streaming kernel at ~6.8 TB/s. sm_103a 256-bit global ld/st
// (2x ld.global.nc.v8.f32 + 2x st.global.v8.f32 per row) + persistent
// grid-stride single-wave launch to eliminate wave-transition drain.

__device__ __forceinline__ void ld256(const float* __restrict__ p, float* r)
{
    asm volatile("ld.global.nc.v8.f32 {%0,%1,%2,%3,%4,%5,%6,%7}, [%8];"
                 : "=f"(r[0]), "=f"(r[1]), "=f"(r[2]), "=f"(r[3]),
                   "=f"(r[4]), "=f"(r[5]), "=f"(r[6]), "=f"(r[7])
                 : "l"(p));
}

__device__ __forceinline__ void st256(float* __restrict__ p, const float* r)
{
    asm volatile("st.global.v8.f32 [%0], {%1,%2,%3,%4,%5,%6,%7,%8};"
                 :: "l"(p),
                    "f"(r[0]), "f"(r[1]), "f"(r[2]), "f"(r[3]),
                    "f"(r[4]), "f"(r[5]), "f"(r[6]), "f"(r[7])
                 : "memory");
}

__global__ void __launch_bounds__(256)
gradewise_ln_kernel(const float* __restrict__ x,
                    const float* __restrict__ scale,
                    float*       __restrict__ out,
                    int nrows)
{
    const float sc0 = __ldg(&scale[0]);
    const float sc1 = __ldg(&scale[1]);
    const float sc2 = __ldg(&scale[2]);
    const float sc3 = __ldg(&scale[3]);
    const float sc4 = __ldg(&scale[4]);

    const int stride = gridDim.x * blockDim.x;

    for (int row = blockIdx.x * blockDim.x + threadIdx.x;
         row < nrows; row += stride)
    {
        size_t base = (size_t)row * 16;

        float v[16];
        ld256(x + base,     v);
        ld256(x + base + 8, v + 8);

        float s0 = v[0] * v[0];
        float s1 = v[1] * v[1] + v[2] * v[2] + v[3] * v[3] + v[4] * v[4];
        float s2 = v[5] * v[5] + v[6] * v[6] + v[7] * v[7]
                 + v[8] * v[8] + v[9] * v[9] + v[10] * v[10];
        float s3 = v[11] * v[11] + v[12] * v[12] + v[13] * v[13] + v[14] * v[14];
        float s4 = v[15] * v[15];

        float r0 = rsqrtf(s0 + EPS) * sc0;
        float r1 = rsqrtf(s1 + EPS) * sc1;
        float r2 = rsqrtf(s2 + EPS) * sc2;
        float r3 = rsqrtf(s3 + EPS) * sc3;
        float r4 = rsqrtf(s4 + EPS) * sc4;

        float o[16];
        o[0]  = v[0]  * r0;
        o[1]  = v[1]  * r1;  o[2]  = v[2]  * r1;  o[3]  = v[3]  * r1;
        o[4]  = v[4]  * r1;
        o[5]  = v[5]  * r2;  o[6]  = v[6]  * r2;  o[7]  = v[7]  * r2;
        o[8]  = v[8]  * r2;  o[9]  = v[9]  * r2;  o[10] = v[10] * r2;
        o[11] = v[11] * r3;  o[12] = v[12] * r3;  o[13] = v[13] * r3;
        o[14] = v[14] * r3;
        o[15] = v[15] * r4;

        st256(out + base,     o);
        st256(out + base + 8, o + 8);
    }
}

extern "C" void kernel_launch(void* const* d_in, const int* in_sizes, int n_in,
                              void* d_out, int out_size)
{
    const float* x     = (const float*)d_in[0];
    const float* scale = (const float*)d_in[1];
    float*       out   = (float*)d_out;

    int nrows = in_sizes[0] / 16;  // 2048*4096 = 8,388,608

    // Single persistent wave: 152 SMs x 8 blocks (32 regs/thread, 256 thr/blk
    // -> 8 blocks/SM occupancy). 1216 blocks covers GB300's 152 SMs fully.
    const int threads = 256;
    const int blocks  = 152 * 8;

    gradewise_ln_kernel<<<blocks, threads>>>(x, scale, out, nrows);
}

// round 7
// speedup vs baseline: 1.1000x; 1.1000x over previous
#include <cuda_runtime.h>

#define EPS 1e-6f

// x: (2048, 4096, 16) fp32  -> 8,388,608 rows of 16 floats (64 B each)
// Grade slices over last dim: [0,1) [1,5) [5,11) [11,15) [15,16)
// out[..., a:b] = x[..., a:b] * rsqrt(sum(x[a:b]^2) + eps) * scale[g]
//
// HBM-streaming kernel. One-shot launch (no grid-stride: CTA scheduler
// provides pipelining), 2 rows/thread with all four 256-bit loads
// front-batched (MLP_p1 = 4) before any compute/store.

__device__ __forceinline__ void ld256(const float* __restrict__ p, float* r)
{
    asm volatile("ld.global.nc.v8.f32 {%0,%1,%2,%3,%4,%5,%6,%7}, [%8];"
                 : "=f"(r[0]), "=f"(r[1]), "=f"(r[2]), "=f"(r[3]),
                   "=f"(r[4]), "=f"(r[5]), "=f"(r[6]), "=f"(r[7])
                 : "l"(p));
}

__device__ __forceinline__ void st256(float* __restrict__ p, const float* r)
{
    asm volatile("st.global.v8.f32 [%0], {%1,%2,%3,%4,%5,%6,%7,%8};"
                 :: "l"(p),
                    "f"(r[0]), "f"(r[1]), "f"(r[2]), "f"(r[3]),
                    "f"(r[4]), "f"(r[5]), "f"(r[6]), "f"(r[7])
                 : "memory");
}

__device__ __forceinline__ void normalize_row(const float* __restrict__ v,
                                              float* __restrict__ o,
                                              float sc0, float sc1, float sc2,
                                              float sc3, float sc4)
{
    float s0 = v[0] * v[0];
    float s1 = v[1] * v[1] + v[2] * v[2] + v[3] * v[3] + v[4] * v[4];
    float s2 = v[5] * v[5] + v[6] * v[6] + v[7] * v[7]
             + v[8] * v[8] + v[9] * v[9] + v[10] * v[10];
    float s3 = v[11] * v[11] + v[12] * v[12] + v[13] * v[13] + v[14] * v[14];
    float s4 = v[15] * v[15];

    float r0 = rsqrtf(s0 + EPS) * sc0;
    float r1 = rsqrtf(s1 + EPS) * sc1;
    float r2 = rsqrtf(s2 + EPS) * sc2;
    float r3 = rsqrtf(s3 + EPS) * sc3;
    float r4 = rsqrtf(s4 + EPS) * sc4;

    o[0]  = v[0]  * r0;
    o[1]  = v[1]  * r1;  o[2]  = v[2]  * r1;  o[3]  = v[3]  * r1;
    o[4]  = v[4]  * r1;
    o[5]  = v[5]  * r2;  o[6]  = v[6]  * r2;  o[7]  = v[7]  * r2;
    o[8]  = v[8]  * r2;  o[9]  = v[9]  * r2;  o[10] = v[10] * r2;
    o[11] = v[11] * r3;  o[12] = v[12] * r3;  o[13] = v[13] * r3;
    o[14] = v[14] * r3;
    o[15] = v[15] * r4;
}

__global__ void __launch_bounds__(256)
gradewise_ln_kernel(const float* __restrict__ x,
                    const float* __restrict__ scale,
                    float*       __restrict__ out,
                    int nrows)
{
    // Block covers 512 consecutive rows; thread t handles rows
    // blk*512 + t and blk*512 + 256 + t (each warp-coalesced).
    int row0 = blockIdx.x * (blockDim.x * 2) + threadIdx.x;
    int row1 = row0 + blockDim.x;

    // nrows is a multiple of 512 (2048*4096 rows, 16384 blocks), but keep
    // guards for safety; the common path has both rows valid.
    if (row1 < nrows) {
        size_t b0 = (size_t)row0 * 16;
        size_t b1 = (size_t)row1 * 16;

        // Front-batch all four 256-bit loads: 4 independent LDGs in flight.
        float va[16], vb[16];
        ld256(x + b0,     va);
        ld256(x + b0 + 8, va + 8);
        ld256(x + b1,     vb);
        ld256(x + b1 + 8, vb + 8);

        float sc0 = __ldg(&scale[0]);
        float sc1 = __ldg(&scale[1]);
        float sc2 = __ldg(&scale[2]);
        float sc3 = __ldg(&scale[3]);
        float sc4 = __ldg(&scale[4]);

        float oa[16], ob[16];
        normalize_row(va, oa, sc0, sc1, sc2, sc3, sc4);
        normalize_row(vb, ob, sc0, sc1, sc2, sc3, sc4);

        st256(out + b0,     oa);
        st256(out + b0 + 8, oa + 8);
        st256(out + b1,     ob);
        st256(out + b1 + 8, ob + 8);
    } else if (row0 < nrows) {
        size_t b0 = (size_t)row0 * 16;
        float va[16];
        ld256(x + b0,     va);
        ld256(x + b0 + 8, va + 8);

        float sc0 = __ldg(&scale[0]);
        float sc1 = __ldg(&scale[1]);
        float sc2 = __ldg(&scale[2]);
        float sc3 = __ldg(&scale[3]);
        float sc4 = __ldg(&scale[4]);

        float oa[16];
        normalize_row(va, oa, sc0, sc1, sc2, sc3, sc4);

        st256(out + b0,     oa);
        st256(out + b0 + 8, oa + 8);
    }
}

extern "C" void kernel_launch(void* const* d_in, const int* in_sizes, int n_in,
                              void* d_out, int out_size)
{
    const float* x     = (const float*)d_in[0];
    const float* scale = (const float*)d_in[1];
    float*       out   = (float*)d_out;

    int nrows = in_sizes[0] / 16;  // 2048*4096 = 8,388,608

    const int threads = 256;
    const int rows_per_block = threads * 2;
    int blocks = (nrows + rows_per_block - 1) / rows_per_block;

    gradewise_ln_kernel<<<blocks, threads>>>(x, scale, out, nrows);
}

// round 8
// speedup vs baseline: 1.1103x; 1.0094x over previous
#include <cuda_runtime.h>

#define EPS 1e-6f

// x: (2048, 4096, 16) fp32  -> 8,388,608 rows of 16 floats (64 B each)
// Grade slices over last dim: [0,1) [1,5) [5,11) [11,15) [15,16)
// out[..., a:b] = x[..., a:b] * rsqrt(sum(x[a:b]^2) + eps) * scale[g]
//
// HBM-streaming kernel (~6.8 TB/s). Best-known shape: one-shot launch,
// 1 row/thread, 2x ld.global.nc.v8.f32 + 2x st.global.cs.v8.f32.
// Stores are evict-first (.cs) so L2 writebacks batch into longer DRAM
// write runs, reducing R/W turnaround.

__device__ __forceinline__ void ld256(const float* __restrict__ p, float* r)
{
    asm volatile("ld.global.nc.v8.f32 {%0,%1,%2,%3,%4,%5,%6,%7}, [%8];"
                 : "=f"(r[0]), "=f"(r[1]), "=f"(r[2]), "=f"(r[3]),
                   "=f"(r[4]), "=f"(r[5]), "=f"(r[6]), "=f"(r[7])
                 : "l"(p));
}

__device__ __forceinline__ void st256cs(float* __restrict__ p, const float* r)
{
    asm volatile("st.global.cs.v8.f32 [%0], {%1,%2,%3,%4,%5,%6,%7,%8};"
                 :: "l"(p),
                    "f"(r[0]), "f"(r[1]), "f"(r[2]), "f"(r[3]),
                    "f"(r[4]), "f"(r[5]), "f"(r[6]), "f"(r[7])
                 : "memory");
}

__global__ void __launch_bounds__(256)
gradewise_ln_kernel(const float* __restrict__ x,
                    const float* __restrict__ scale,
                    float*       __restrict__ out,
                    int nrows)
{
    int row = blockIdx.x * blockDim.x + threadIdx.x;
    if (row >= nrows) return;

    size_t base = (size_t)row * 16;

    float v[16];
    ld256(x + base,     v);
    ld256(x + base + 8, v + 8);

    // grade sums of squares over slices [0,1) [1,5) [5,11) [11,15) [15,16)
    float s0 = v[0] * v[0];
    float s1 = v[1] * v[1] + v[2] * v[2] + v[3] * v[3] + v[4] * v[4];
    float s2 = v[5] * v[5] + v[6] * v[6] + v[7] * v[7]
             + v[8] * v[8] + v[9] * v[9] + v[10] * v[10];
    float s3 = v[11] * v[11] + v[12] * v[12] + v[13] * v[13] + v[14] * v[14];
    float s4 = v[15] * v[15];

    float r0 = rsqrtf(s0 + EPS) * __ldg(&scale[0]);
    float r1 = rsqrtf(s1 + EPS) * __ldg(&scale[1]);
    float r2 = rsqrtf(s2 + EPS) * __ldg(&scale[2]);
    float r3 = rsqrtf(s3 + EPS) * __ldg(&scale[3]);
    float r4 = rsqrtf(s4 + EPS) * __ldg(&scale[4]);

    float o[16];
    o[0]  = v[0]  * r0;
    o[1]  = v[1]  * r1;  o[2]  = v[2]  * r1;  o[3]  = v[3]  * r1;
    o[4]  = v[4]  * r1;
    o[5]  = v[5]  * r2;  o[6]  = v[6]  * r2;  o[7]  = v[7]  * r2;
    o[8]  = v[8]  * r2;  o[9]  = v[9]  * r2;  o[10] = v[10] * r2;
    o[11] = v[11] * r3;  o[12] = v[12] * r3;  o[13] = v[13] * r3;
    o[14] = v[14] * r3;
    o[15] = v[15] * r4;

    st256cs(out + base,     o);
    st256cs(out + base + 8, o + 8);
}

extern "C" void kernel_launch(void* const* d_in, const int* in_sizes, int n_in,
                              void* d_out, int out_size)
{
    const float* x     = (const float*)d_in[0];
    const float* scale = (const float*)d_in[1];
    float*       out   = (float*)d_out;

    int nrows = in_sizes[0] / 16;  // 2048*4096 = 8,388,608

    const int threads = 256;
    int blocks = (nrows + threads - 1) / threads;

    gradewise_ln_kernel<<<blocks, threads>>>(x, scale, out, nrows);
}